// round 1
// baseline (speedup 1.0000x reference)
#include <cuda_runtime.h>
#include <stdint.h>

// TernaryLinear: out = (x @ ternary(W).T + bias) * scale
//   x: [N, 4096] fp32, W: [4096, 4096] fp32, scale/bias: [4096] fp32
//   ternary(W) = 0 where |W| < 0.1f else sign(W)
//
// Strategy: W ~ U(-0.1, 0.1) means the ternary matrix is (near-)empty — only
// exact-endpoint draws survive the threshold. Compress ternary(W) to per-output
// -column (index, sign) lists, then the output is an exact fp32 gather-sum.
// Worst case (dense ternary) still correct: list capacity = full 4096/column.

#define IN_DIM  4096
#define OUT_DIM 4096
#define ROWS_PER_BLOCK 8

// Scratch: per-column nonzero counts + packed (idx<<1 | neg) lists.
// Worst case 4096 entries/column * 4096 columns * 4B = 64 MB static scratch.
__device__ int g_count[OUT_DIM];
__device__ int g_list[(size_t)OUT_DIM * IN_DIM];

// ---------------------------------------------------------------------------
// Kernel Z: reset counters (graph is replayed; state must be rebuilt each call)
// ---------------------------------------------------------------------------
__global__ void tl_zero_counts() {
    g_count[blockIdx.x * blockDim.x + threadIdx.x] = 0;
}

// ---------------------------------------------------------------------------
// Kernel A: ternarize + compress. One pass over 64 MB of weights (float4).
// Nonzero condition replicates the reference exactly: !(|w| < 0.1f).
// ---------------------------------------------------------------------------
__global__ void tl_compress(const float* __restrict__ w) {
    const int total4 = (OUT_DIM * IN_DIM) / 4;
    int stride = gridDim.x * blockDim.x;
    for (int j = blockIdx.x * blockDim.x + threadIdx.x; j < total4; j += stride) {
        float4 v = reinterpret_cast<const float4*>(w)[j];
        float vals[4] = {v.x, v.y, v.z, v.w};
        int base = j * 4;
#pragma unroll
        for (int k = 0; k < 4; k++) {
            float wv = vals[k];
            if (!(fabsf(wv) < 0.1f)) {          // survives threshold -> +-1
                int lin = base + k;
                int o = lin >> 12;              // row of W = output channel
                int i = lin & (IN_DIM - 1);     // input index
                int pos = atomicAdd(&g_count[o], 1);
                g_list[((size_t)o << 12) + pos] = (i << 1) | (wv < 0.0f ? 1 : 0);
            }
        }
    }
}

// ---------------------------------------------------------------------------
// Kernel B: exact fp32 gather-sum + epilogue. Coalesced output writes
// (threads sweep o), 8 n-rows per block to amortize count/scale/bias loads.
// ---------------------------------------------------------------------------
__global__ void tl_output(const float* __restrict__ x,
                          const float* __restrict__ scale,
                          const float* __restrict__ bias,
                          float* __restrict__ out, int N) {
    int o = blockIdx.x * blockDim.x + threadIdx.x;   // 0..4095
    int n0 = blockIdx.y * ROWS_PER_BLOCK;

    int   c = g_count[o];
    float b = bias[o];
    float s = scale[o];
    const int* lst = &g_list[(size_t)o << 12];

#pragma unroll
    for (int r = 0; r < ROWS_PER_BLOCK; r++) {
        int n = n0 + r;
        if (n >= N) break;
        const float* xr = x + (size_t)n * IN_DIM;
        float acc = 0.0f;
        for (int k = 0; k < c; k++) {
            int v = lst[k];
            float xv = __ldg(&xr[v >> 1]);
            acc += (v & 1) ? -xv : xv;
        }
        out[(size_t)n * OUT_DIM + o] = (acc + b) * s;
    }
}

// ---------------------------------------------------------------------------
extern "C" void kernel_launch(void* const* d_in, const int* in_sizes, int n_in,
                              void* d_out, int out_size) {
    const float* x     = (const float*)d_in[0];
    const float* w     = (const float*)d_in[1];
    const float* scale = (const float*)d_in[2];
    const float* bias  = (const float*)d_in[3];
    float* out = (float*)d_out;

    int N = in_sizes[0] / IN_DIM;   // 8192

    tl_zero_counts<<<OUT_DIM / 256, 256>>>();
    tl_compress<<<148 * 8, 256>>>(w);
    dim3 grid(OUT_DIM / 256, (N + ROWS_PER_BLOCK - 1) / ROWS_PER_BLOCK);
    tl_output<<<grid, 256>>>(x, scale, bias, out, N);
}